// round 12
// baseline (speedup 1.0000x reference)
#include <cuda_runtime.h>
#include <cuda_pipeline.h>
#include <math.h>

#define NN 10000
#define NN2 10048          // padded row count for scratch
#define NF 128
#define NH 64
#define MAXNNZ 2000000

// ---------------- scratch (device globals, no allocation) ----------------
// Interleaved layouts: row stride 128 floats; cols [0,64) = outcome path,
// cols [64,128) = treatment path.
__device__ __align__(16) float g_AB[NN2 * 128];   // P buffers (gemm out)
__device__ __align__(16) float g_CD[NN2 * 128];   // rep buffers (spmm out)
__device__ __align__(16) float g_R[NN2 * NH];     // rep_out

struct __align__(8) Edge { int c; float v; };

__device__ int   g_rowbase[NN];
__device__ int   g_rownnz[NN];
__device__ Edge  g_edge[MAXNNZ];
__device__ int   g_top = 0;

__device__ __align__(16) float g_ssrc[NN];
__device__ __align__(16) float g_sdst[NN];
__device__ __align__(16) float g_part[250 * NH];
__device__ __align__(16) float g_Sall[NH];

struct GemmArgs {
    const float* X[2];
    const float* W[2];
    float*       out[2];   // already offset by m*64; row stride 128
    int          xs;       // X row stride (floats)
};

// ---------------- GEMM tile body: 32 rows x 64 cols, Xs transposed ----------------
template <int K>
__device__ __forceinline__ void gemm_tile(const float* __restrict__ X, int xstride,
                                          const float* __restrict__ W,
                                          float* __restrict__ O,
                                          int bx, int tid,
                                          float* Xs /*64*34*/, float* Ws /*64*64*/) {
    int tx = tid & 15, ty = tid >> 4;
    int r0 = bx * 32;
    float acc[2][4] = {};

    for (int k0 = 0; k0 < K; k0 += 64) {
        {
            const float4* s = (const float4*)(W + (size_t)k0 * 64);
            float4* d = (float4*)Ws;
            #pragma unroll
            for (int i = 0; i < 4; i++) d[tid + 256 * i] = s[tid + 256 * i];
        }
        #pragma unroll
        for (int i = 0; i < 2; i++) {
            int e = tid + 256 * i;
            int row = e >> 4, c4 = e & 15;
            int rr = r0 + row;
            float4 v = make_float4(0.f, 0.f, 0.f, 0.f);
            if (rr < NN) v = ((const float4*)(X + (size_t)rr * xstride + k0))[c4];
            int kk = c4 * 4;
            Xs[(kk + 0) * 34 + row] = v.x;
            Xs[(kk + 1) * 34 + row] = v.y;
            Xs[(kk + 2) * 34 + row] = v.z;
            Xs[(kk + 3) * 34 + row] = v.w;
        }
        __syncthreads();
        #pragma unroll 8
        for (int k = 0; k < 64; k++) {
            float4 wv = *(const float4*)&Ws[k * 64 + tx * 4];
            float2 xv = *(const float2*)&Xs[k * 34 + ty * 2];
            acc[0][0] += xv.x * wv.x; acc[0][1] += xv.x * wv.y;
            acc[0][2] += xv.x * wv.z; acc[0][3] += xv.x * wv.w;
            acc[1][0] += xv.y * wv.x; acc[1][1] += xv.y * wv.y;
            acc[1][2] += xv.y * wv.z; acc[1][3] += xv.y * wv.w;
        }
        __syncthreads();
    }
    #pragma unroll
    for (int i = 0; i < 2; i++) {
        int rr = r0 + ty * 2 + i;
        if (rr >= NN) continue;
        float4 o = make_float4(acc[i][0], acc[i][1], acc[i][2], acc[i][3]);
        *(float4*)(O + (size_t)rr * 128 + tx * 4) = o;
    }
}

// ---------------- merged: sparsify (blocks 0..9999) + layer-1 GEMM ----------------
__global__ void __launch_bounds__(256) k_spg(const float* __restrict__ adj, GemmArgs ga) {
    __shared__ float Xs[64 * 34];
    __shared__ float Ws[64 * 64];
    __shared__ int wsum[8];
    __shared__ int sbase;

    int t = threadIdx.x;

    if (blockIdx.x >= NN) {
        int b = blockIdx.x - NN;        // 0..625
        int m = b >= 313;
        int bx = m ? b - 313 : b;
        gemm_tile<128>(ga.X[m], ga.xs, ga.W[m], ga.out[m], bx, t, Xs, Ws);
        return;
    }

    // ---- sparsify role ----
    int row = blockIdx.x;
    const float4* rp = (const float4*)(adj + (size_t)row * NN);
    int lane = t & 31, wid = t >> 5;

    float4 v[10];
    #pragma unroll
    for (int i = 0; i < 10; i++) {
        int j = t + 256 * i;
        if (j < NN / 4) v[i] = __ldcs(rp + j);
        else            v[i] = make_float4(0.f, 0.f, 0.f, 0.f);
    }

    int c = 0;
    #pragma unroll
    for (int i = 0; i < 10; i++)
        c += (v[i].x != 0.f) + (v[i].y != 0.f) + (v[i].z != 0.f) + (v[i].w != 0.f);

    int s = c;
    #pragma unroll
    for (int d = 1; d < 32; d <<= 1) {
        int n = __shfl_up_sync(0xffffffffu, s, d);
        if (lane >= d) s += n;
    }
    if (lane == 31) wsum[wid] = s;
    __syncthreads();
    int wbase = 0;
    #pragma unroll
    for (int i = 0; i < 8; i++) wbase += (i < wid) ? wsum[i] : 0;
    int excl = wbase + s - c;
    if (t == 0) {
        int tot = 0;
        #pragma unroll
        for (int i = 0; i < 8; i++) tot += wsum[i];
        int b = atomicAdd(&g_top, tot);
        g_rowbase[row] = b;
        g_rownnz[row]  = tot;
        sbase = b;
    }
    __syncthreads();

    int dst = sbase + excl;
    #pragma unroll
    for (int i = 0; i < 10; i++) {
        int cb = (t + 256 * i) * 4;
        if (v[i].x != 0.f) { g_edge[dst].c = cb + 0; g_edge[dst].v = v[i].x; dst++; }
        if (v[i].y != 0.f) { g_edge[dst].c = cb + 1; g_edge[dst].v = v[i].y; dst++; }
        if (v[i].z != 0.f) { g_edge[dst].c = cb + 2; g_edge[dst].v = v[i].z; dst++; }
        if (v[i].w != 0.f) { g_edge[dst].c = cb + 3; g_edge[dst].v = v[i].w; dst++; }
    }
}

// ---------------- standalone GEMM (layer 2) ----------------
template <int K>
__global__ void __launch_bounds__(256) k_gemm(GemmArgs ga) {
    __shared__ float Xs[64 * 34];
    __shared__ float Ws[64 * 64];
    int m = blockIdx.y;
    gemm_tile<K>(ga.X[m], ga.xs, ga.W[m], ga.out[m], blockIdx.x, threadIdx.x, Xs, Ws);
}

// ---------------- SpMM: warp-autonomous, 1 warp = 1 row (both paths) ----------------
// lane l covers floats 4l..4l+3 of the interleaved 128-float row pair.
// Edges staged in registers, broadcast by shfl, 8 gathers in flight.
__global__ void __launch_bounds__(256) k_spmm(const float* __restrict__ b0,
                                              const float* __restrict__ b1,
                                              int layer2, const float* __restrict__ a) {
    int w = threadIdx.x >> 5, l = threadIdx.x & 31;
    int row = blockIdx.x * 8 + w;
    int base = g_rowbase[row], nnz = g_rownnz[row];
    const float4* __restrict__ AB4 = (const float4*)g_AB;

    float4 acc0 = make_float4(0.f, 0.f, 0.f, 0.f), acc1 = acc0;
    for (int c0 = 0; c0 < nnz; c0 += 32) {
        int j = nnz - c0; if (j > 32) j = 32;
        Edge my;
        if (l < j) my = g_edge[base + c0 + l];
        else       { my.c = 0; my.v = 0.f; }
        int ng = (j + 7) & ~7;          // groups of 8, padded lanes carry v=0
        for (int e = 0; e < ng; e += 8) {
            #pragma unroll
            for (int u = 0; u < 8; u++) {
                int   cc = __shfl_sync(0xffffffffu, my.c, e + u);
                float vv = __shfl_sync(0xffffffffu, my.v, e + u);
                float4 p = AB4[(size_t)cc * 32 + l];
                if (u & 1) {
                    acc1.x += vv * p.x; acc1.y += vv * p.y;
                    acc1.z += vv * p.z; acc1.w += vv * p.w;
                } else {
                    acc0.x += vv * p.x; acc0.y += vv * p.y;
                    acc0.z += vv * p.z; acc0.w += vv * p.w;
                }
            }
        }
    }
    float4 bv = (l < 16) ? ((const float4*)b0)[l] : ((const float4*)b1)[l - 16];
    float4 sum;
    sum.x = fmaxf(acc0.x + acc1.x + bv.x, 0.f);
    sum.y = fmaxf(acc0.y + acc1.y + bv.y, 0.f);
    sum.z = fmaxf(acc0.z + acc1.z + bv.z, 0.f);
    sum.w = fmaxf(acc0.w + acc1.w + bv.w, 0.f);
    ((float4*)g_CD)[(size_t)row * 32 + l] = sum;

    if (layer2) {
        // rep_cat layout == CD row layout: [o(64); t(64)]; lane l covers 4l..4l+3
        float4 as = ((const float4*)a)[l];        // a[0..127]   (src)
        float4 ad = ((const float4*)a)[l + 32];   // a[128..255] (dst)
        float rs = sum.x * as.x + sum.y * as.y + sum.z * as.z + sum.w * as.w;
        float rd = sum.x * ad.x + sum.y * ad.y + sum.z * ad.z + sum.w * ad.w;
        #pragma unroll
        for (int o = 16; o; o >>= 1) {
            rs += __shfl_xor_sync(0xffffffffu, rs, o);
            rd += __shfl_xor_sync(0xffffffffu, rd, o);
        }
        if (l == 0) { g_ssrc[row] = rs; g_sdst[row] = rd; }
    }
}

// ---------------- column sum of rep_t (deterministic 2-stage) ----------------
__global__ void k_colsum_part() {
    int b = blockIdx.x;   // 250 blocks x 40 rows
    int h = threadIdx.x;
    int r0 = b * 40;
    float acc = 0.f;
    #pragma unroll 4
    for (int r = r0; r < r0 + 40; r++) acc += g_CD[(size_t)r * 128 + 64 + h];
    g_part[b * 64 + h] = acc;
}
__global__ void k_colsum_comb() {
    int h = threadIdx.x;
    float acc = 0.f;
    for (int b = 0; b < 250; b++) acc += g_part[b * 64 + h];
    g_Sall[h] = acc;
}

// ---------------- attention: warp-per-row, shfl-broadcast edges, exp once ----------------
__global__ void __launch_bounds__(256) k_att(float* __restrict__ dout) {
    int w = threadIdx.x >> 5, l = threadIdx.x & 31;
    int row = blockIdx.x * 8 + w;
    int half = l >> 4, q = l & 15;
    int base = g_rowbase[row], nnz = g_rownnz[row];
    float si = g_ssrc[row];

    // pass 1: row max of sdst over edges (each staging lane contributes its edge)
    float lm = -1e30f;
    for (int c0 = 0; c0 < nnz; c0 += 32) {
        int j = nnz - c0; if (j > 32) j = 32;
        if (l < j) lm = fmaxf(lm, g_sdst[g_edge[base + c0 + l].c]);
    }
    #pragma unroll
    for (int o = 16; o; o >>= 1)
        lm = fmaxf(lm, __shfl_xor_sync(0xffffffffu, lm, o));
    float mm = fmaxf(si + lm, 0.f);

    // pass 2: weighted/plain gather of treatment half (256B via 16 lanes x float4)
    const float4* __restrict__ CD4 = (const float4*)g_CD;
    float4 aW = make_float4(0.f, 0.f, 0.f, 0.f), aR = aW;
    float sw = 0.f;
    for (int c0 = 0; c0 < nnz; c0 += 32) {
        int j = nnz - c0; if (j > 32) j = 32;
        Edge my;
        float wv_my = 0.f;
        if (l < j) {
            my = g_edge[base + c0 + l];
            wv_my = __expf(si + g_sdst[my.c] - mm);
        } else my.c = 0;
        int kmax = (j - half + 1) >> 1;    // this half handles edges half, half+2, ...
        #pragma unroll 4
        for (int kk = 0; kk < kmax; kk++) {
            int e = half + 2 * kk;
            int   cc = __shfl_sync(0xffffffffu, my.c, e);
            float wv = __shfl_sync(0xffffffffu, wv_my, e);
            float4 p = CD4[(size_t)cc * 32 + 16 + q];
            aW.x += wv * p.x; aW.y += wv * p.y; aW.z += wv * p.z; aW.w += wv * p.w;
            aR.x += p.x;      aR.y += p.y;      aR.z += p.z;      aR.w += p.w;
            sw += wv;
        }
    }
    // combine halves
    sw   += __shfl_xor_sync(0xffffffffu, sw, 16);
    aW.x += __shfl_xor_sync(0xffffffffu, aW.x, 16);
    aW.y += __shfl_xor_sync(0xffffffffu, aW.y, 16);
    aW.z += __shfl_xor_sync(0xffffffffu, aW.z, 16);
    aW.w += __shfl_xor_sync(0xffffffffu, aW.w, 16);
    aR.x += __shfl_xor_sync(0xffffffffu, aR.x, 16);
    aR.y += __shfl_xor_sync(0xffffffffu, aR.y, 16);
    aR.z += __shfl_xor_sync(0xffffffffu, aR.z, 16);
    aR.w += __shfl_xor_sync(0xffffffffu, aR.w, 16);

    float em = __expf(-mm);
    float denom = (float)(NN - nnz) * em + sw;
    if (half == 0) {
        float4 S = ((const float4*)g_Sall)[q];
        float4 C = CD4[(size_t)row * 32 + q];
        float4 v;
        v.x = (em * (S.x - aR.x) + aW.x) / denom + C.x;
        v.y = (em * (S.y - aR.y) + aW.y) / denom + C.y;
        v.z = (em * (S.z - aR.z) + aW.z) / denom + C.z;
        v.w = (em * (S.w - aR.w) + aW.w) / denom + C.w;
        ((float4*)(dout + 10000))[(size_t)row * 16 + q] = v;
        ((float4*)g_R)[(size_t)row * 16 + q] = v;
    }
}

// ---------------- fused heads: 5 GEMMs, cp.async double-buffered weights ----------------
__global__ void __launch_bounds__(256) k_heads(
        const int* __restrict__ t,
        const float* __restrict__ W000, const float* __restrict__ b000,
        const float* __restrict__ W001, const float* __restrict__ b001,
        const float* __restrict__ W100, const float* __restrict__ b100,
        const float* __restrict__ W101, const float* __restrict__ b101,
        const float* __restrict__ Wo0,  const float* __restrict__ bo0,
        const float* __restrict__ Wo1,  const float* __restrict__ bo1,
        const float* __restrict__ Wpp,  const float* __restrict__ bpp,
        const float* __restrict__ Wpp2, const float* __restrict__ bpp2,
        float* __restrict__ dout) {
    __shared__ float U[64 * 65];
    __shared__ float V[64 * 65];
    __shared__ __align__(16) float WsA[64 * 64];
    __shared__ __align__(16) float WsB[64 * 64];
    __shared__ float sWv0[64], sWv1[64];
    __shared__ float yy[2][64];

    int tid = threadIdx.x;
    int tx = tid & 15, ty = tid >> 4;
    int r0 = blockIdx.x * 64;

    auto loadW_async = [&](const float* W, float* dst) {
        #pragma unroll
        for (int i = 0; i < 4; i++)
            __pipeline_memcpy_async((float4*)dst + tid + 256 * i,
                                    (const float4*)W + tid + 256 * i, 16);
        __pipeline_commit();
    };
    auto loadX = [&](const float* X, int stride, float* dst) {
        #pragma unroll
        for (int i = 0; i < 4; i++) {
            int e = tid + 256 * i;
            int row = e >> 4, c4 = e & 15;
            float4 v = ((const float4*)(X + (size_t)(r0 + row) * stride))[c4];
            dst[row * 65 + c4 * 4 + 0] = v.x;
            dst[row * 65 + c4 * 4 + 1] = v.y;
            dst[row * 65 + c4 * 4 + 2] = v.z;
            dst[row * 65 + c4 * 4 + 3] = v.w;
        }
    };
    auto stage = [&](const float* in, float* outp, const float* Ws,
                     const float* b, bool relu) {
        float acc[4][4] = {};
        #pragma unroll 4
        for (int k = 0; k < 64; k++) {
            float4 wv = *(const float4*)&Ws[k * 64 + tx * 4];
            float xv[4];
            #pragma unroll
            for (int i = 0; i < 4; i++) xv[i] = in[(ty * 4 + i) * 65 + k];
            #pragma unroll
            for (int i = 0; i < 4; i++) {
                acc[i][0] += xv[i] * wv.x; acc[i][1] += xv[i] * wv.y;
                acc[i][2] += xv[i] * wv.z; acc[i][3] += xv[i] * wv.w;
            }
        }
        #pragma unroll
        for (int i = 0; i < 4; i++)
            #pragma unroll
            for (int j = 0; j < 4; j++) {
                float vv = acc[i][j] + b[tx * 4 + j];
                if (relu) vv = fmaxf(vv, 0.f);
                outp[(ty * 4 + i) * 65 + tx * 4 + j] = vv;
            }
    };

    loadW_async(W000, WsA);
    loadX((const float*)g_R, 64, U);
    if (tid < 64)            sWv0[tid]      = Wo0[tid];
    else if (tid < 128)      sWv1[tid - 64] = Wo1[tid - 64];
    __pipeline_wait_prior(0);
    __syncthreads();

    loadW_async(W001, WsB);
    stage(U, V, WsA, b000, true);
    __pipeline_wait_prior(0);
    __syncthreads();

    loadW_async(W100, WsA);
    stage(V, U, WsB, b001, true);
    __pipeline_wait_prior(0);
    __syncthreads();

    // yy0 from U; reload g_R into V (V is free)
    if (tid < 64) {
        float acc = 0.f;
        #pragma unroll 4
        for (int k = 0; k < 64; k++) acc += U[tid * 65 + k] * sWv0[k];
        yy[0][tid] = acc;
    }
    loadX((const float*)g_R, 64, V);
    __syncthreads();

    loadW_async(W101, WsB);
    stage(V, U, WsA, b100, true);
    __pipeline_wait_prior(0);
    __syncthreads();

    loadW_async(Wpp, WsA);
    stage(U, V, WsB, b101, true);
    __pipeline_wait_prior(0);
    __syncthreads();

    // yy1 from V; reload treatment rep into U (U is free)
    if (tid < 64) {
        float acc = 0.f;
        #pragma unroll 4
        for (int k = 0; k < 64; k++) acc += V[tid * 65 + k] * sWv1[k];
        yy[1][tid] = acc;
    }
    loadX((const float*)g_CD + 64, 128, U);
    __syncthreads();

    stage(U, V, WsA, bpp, false);
    __syncthreads();

    if (tid < 64) {
        int row = r0 + tid;
        if (row < NN) {
            float z0 = 0.f, z1 = 0.f;
            #pragma unroll 4
            for (int k = 0; k < 64; k++) {
                float e = V[tid * 65 + k];
                z0 += e * Wpp2[k * 2];
                z1 += e * Wpp2[k * 2 + 1];
            }
            dout[650000 + (size_t)row * 2 + 0] = 1.f / (1.f + __expf(-(z0 + bpp2[0])));
            dout[650000 + (size_t)row * 2 + 1] = 1.f / (1.f + __expf(-(z1 + bpp2[1])));
            dout[row] = (t[row] > 0) ? (yy[1][tid] + bo1[0]) : (yy[0][tid] + bo0[0]);
        }
    }
    if (blockIdx.x == 0 && tid == 0) g_top = 0;
}

// ---------------- launch ----------------
extern "C" void kernel_launch(void* const* d_in, const int* in_sizes, int n_in,
                              void* d_out, int out_size) {
    const float* x    = (const float*)d_in[0];
    const float* adj  = (const float*)d_in[1];
    const int*   t    = (const int*)d_in[2];
    const float* Wg0  = (const float*)d_in[3];
    const float* bg0  = (const float*)d_in[4];
    const float* Wg1  = (const float*)d_in[5];
    const float* bg1  = (const float*)d_in[6];
    const float* Wt0  = (const float*)d_in[7];
    const float* bt0  = (const float*)d_in[8];
    const float* Wt1  = (const float*)d_in[9];
    const float* bt1  = (const float*)d_in[10];
    const float* W000 = (const float*)d_in[11];
    const float* b000 = (const float*)d_in[12];
    const float* W001 = (const float*)d_in[13];
    const float* b001 = (const float*)d_in[14];
    const float* W100 = (const float*)d_in[15];
    const float* b100 = (const float*)d_in[16];
    const float* W101 = (const float*)d_in[17];
    const float* b101 = (const float*)d_in[18];
    const float* Wo0  = (const float*)d_in[19];
    const float* bo0  = (const float*)d_in[20];
    const float* Wo1  = (const float*)d_in[21];
    const float* bo1  = (const float*)d_in[22];
    const float* Wpp  = (const float*)d_in[23];
    const float* bpp  = (const float*)d_in[24];
    const float* Wpp2 = (const float*)d_in[25];
    const float* bpp2 = (const float*)d_in[26];
    const float* a    = (const float*)d_in[27];
    float* out = (float*)d_out;

    float* pAB; cudaGetSymbolAddress((void**)&pAB, g_AB);
    float* pCD; cudaGetSymbolAddress((void**)&pCD, g_CD);

    // merged sparsify + layer-1 GEMM
    {
        GemmArgs ga = {};
        ga.X[0] = x;   ga.X[1] = x;
        ga.W[0] = Wg0; ga.W[1] = Wt0;
        ga.out[0] = pAB; ga.out[1] = pAB + 64;
        ga.xs = 128;
        k_spg<<<NN + 626, 256>>>(adj, ga);
    }
    k_spmm<<<1250, 256>>>(bg0, bt0, 0, nullptr);

    // layer 2
    {
        GemmArgs ga = {};
        ga.X[0] = pCD;  ga.X[1] = pCD + 64;
        ga.W[0] = Wg1; ga.W[1] = Wt1;
        ga.out[0] = pAB; ga.out[1] = pAB + 64;
        ga.xs = 128;
        k_gemm<64><<<dim3(313, 2), 256>>>(ga);
    }
    k_spmm<<<1250, 256>>>(bg1, bt1, 1, a);   // + fused scores

    k_colsum_part<<<250, 64>>>();
    k_colsum_comb<<<1, 64>>>();
    k_att<<<1250, 256>>>(out);

    k_heads<<<157, 256>>>(t, W000, b000, W001, b001, W100, b100, W101, b101,
                          Wo0, bo0, Wo1, bo1, Wpp, bpp, Wpp2, bpp2, out);
}

// round 15
// speedup vs baseline: 1.1040x; 1.1040x over previous
#include <cuda_runtime.h>
#include <math.h>

#define NN 10000
#define NN2 10048          // padded row count for scratch
#define NF 128
#define NH 64
#define MAXNNZ 2000000

// ---------------- scratch (device globals, no allocation) ----------------
// Interleaved layouts: row stride 128 floats; cols [0,64) = outcome path,
// cols [64,128) = treatment path.
__device__ __align__(16) float g_AB[NN2 * 128];   // P buffers (gemm out)
__device__ __align__(16) float g_CD[NN2 * 128];   // rep buffers (spmm out)
__device__ __align__(16) float g_R[NN2 * NH];     // rep_out

struct __align__(8) Edge { int c; float v; };

__device__ int   g_rowbase[NN];
__device__ int   g_rownnz[NN];
__device__ Edge  g_edge[MAXNNZ];
__device__ int   g_top = 0;
__device__ int   g_ccnt = 0;

__device__ __align__(16) float g_ssrc[NN];
__device__ __align__(16) float g_sdst[NN];
__device__ __align__(16) float g_part[250 * NH];
__device__ __align__(16) float g_Sall[NH];

struct GemmArgs {
    const float* X[2];
    const float* W[2];
    float*       out[2];   // already offset by m*64; row stride 128
    int          xs;       // X row stride (floats)
};

// ---------------- GEMM tile body: 32 rows x 64 cols, Xs transposed ----------------
template <int K>
__device__ __forceinline__ void gemm_tile(const float* __restrict__ X, int xstride,
                                          const float* __restrict__ W,
                                          float* __restrict__ O,
                                          int bx, int tid,
                                          float* Xs /*64*34*/, float* Ws /*64*64*/) {
    int tx = tid & 15, ty = tid >> 4;
    int r0 = bx * 32;
    float acc[2][4] = {};

    for (int k0 = 0; k0 < K; k0 += 64) {
        {
            const float4* s = (const float4*)(W + (size_t)k0 * 64);
            float4* d = (float4*)Ws;
            #pragma unroll
            for (int i = 0; i < 4; i++) d[tid + 256 * i] = s[tid + 256 * i];
        }
        #pragma unroll
        for (int i = 0; i < 2; i++) {
            int e = tid + 256 * i;
            int row = e >> 4, c4 = e & 15;
            int rr = r0 + row;
            float4 v = make_float4(0.f, 0.f, 0.f, 0.f);
            if (rr < NN) v = ((const float4*)(X + (size_t)rr * xstride + k0))[c4];
            int kk = c4 * 4;
            Xs[(kk + 0) * 34 + row] = v.x;
            Xs[(kk + 1) * 34 + row] = v.y;
            Xs[(kk + 2) * 34 + row] = v.z;
            Xs[(kk + 3) * 34 + row] = v.w;
        }
        __syncthreads();
        #pragma unroll 8
        for (int k = 0; k < 64; k++) {
            float4 wv = *(const float4*)&Ws[k * 64 + tx * 4];
            float2 xv = *(const float2*)&Xs[k * 34 + ty * 2];
            acc[0][0] += xv.x * wv.x; acc[0][1] += xv.x * wv.y;
            acc[0][2] += xv.x * wv.z; acc[0][3] += xv.x * wv.w;
            acc[1][0] += xv.y * wv.x; acc[1][1] += xv.y * wv.y;
            acc[1][2] += xv.y * wv.z; acc[1][3] += xv.y * wv.w;
        }
        __syncthreads();
    }
    #pragma unroll
    for (int i = 0; i < 2; i++) {
        int rr = r0 + ty * 2 + i;
        if (rr >= NN) continue;
        float4 o = make_float4(acc[i][0], acc[i][1], acc[i][2], acc[i][3]);
        *(float4*)(O + (size_t)rr * 128 + tx * 4) = o;
    }
}

// ---------------- merged: sparsify (blocks 0..9999) + layer-1 GEMM ----------------
__global__ void __launch_bounds__(256) k_spg(const float* __restrict__ adj, GemmArgs ga) {
    __shared__ float Xs[64 * 34];
    __shared__ float Ws[64 * 64];
    __shared__ int wsum[8];
    __shared__ int sbase;

    int t = threadIdx.x;

    if (blockIdx.x >= NN) {
        int b = blockIdx.x - NN;        // 0..625
        int m = b >= 313;
        int bx = m ? b - 313 : b;
        gemm_tile<128>(ga.X[m], ga.xs, ga.W[m], ga.out[m], bx, t, Xs, Ws);
        return;
    }

    // ---- sparsify role ----
    int row = blockIdx.x;
    const float4* rp = (const float4*)(adj + (size_t)row * NN);
    int lane = t & 31, wid = t >> 5;

    float4 v[10];
    #pragma unroll
    for (int i = 0; i < 10; i++) {
        int j = t + 256 * i;
        if (j < NN / 4) v[i] = __ldcs(rp + j);
        else            v[i] = make_float4(0.f, 0.f, 0.f, 0.f);
    }

    int c = 0;
    #pragma unroll
    for (int i = 0; i < 10; i++)
        c += (v[i].x != 0.f) + (v[i].y != 0.f) + (v[i].z != 0.f) + (v[i].w != 0.f);

    int s = c;
    #pragma unroll
    for (int d = 1; d < 32; d <<= 1) {
        int n = __shfl_up_sync(0xffffffffu, s, d);
        if (lane >= d) s += n;
    }
    if (lane == 31) wsum[wid] = s;
    __syncthreads();
    int wbase = 0;
    #pragma unroll
    for (int i = 0; i < 8; i++) wbase += (i < wid) ? wsum[i] : 0;
    int excl = wbase + s - c;
    if (t == 0) {
        int tot = 0;
        #pragma unroll
        for (int i = 0; i < 8; i++) tot += wsum[i];
        int b = atomicAdd(&g_top, tot);
        g_rowbase[row] = b;
        g_rownnz[row]  = tot;
        sbase = b;
    }
    __syncthreads();

    int dst = sbase + excl;
    #pragma unroll
    for (int i = 0; i < 10; i++) {
        int cb = (t + 256 * i) * 4;
        if (v[i].x != 0.f) { g_edge[dst].c = cb + 0; g_edge[dst].v = v[i].x; dst++; }
        if (v[i].y != 0.f) { g_edge[dst].c = cb + 1; g_edge[dst].v = v[i].y; dst++; }
        if (v[i].z != 0.f) { g_edge[dst].c = cb + 2; g_edge[dst].v = v[i].z; dst++; }
        if (v[i].w != 0.f) { g_edge[dst].c = cb + 3; g_edge[dst].v = v[i].w; dst++; }
    }
}

// ---------------- standalone GEMM (layer 2) ----------------
template <int K>
__global__ void __launch_bounds__(256) k_gemm(GemmArgs ga) {
    __shared__ float Xs[64 * 34];
    __shared__ float Ws[64 * 64];
    int m = blockIdx.y;
    gemm_tile<K>(ga.X[m], ga.xs, ga.W[m], ga.out[m], blockIdx.x, threadIdx.x, Xs, Ws);
}

// ---------------- fused SpMM (+bias+relu), both paths via interleaved float4 (R10) ----------------
__global__ void k_spmm(const float* __restrict__ b0, const float* __restrict__ b1,
                       int layer2, const float* __restrict__ a) {
    int row = blockIdx.x;
    int tid = threadIdx.x;          // 64
    int w = tid >> 5, l = tid & 31;
    int base = g_rowbase[row], nnz = g_rownnz[row];
    const float4* __restrict__ AB4 = (const float4*)g_AB;

    __shared__ Edge se[64];
    __shared__ __align__(16) float sbias[128];
    __shared__ float4 red[32];
    __shared__ __align__(16) float srep[128];
    __shared__ float xr[2], xd[2];

    sbias[tid]      = b0[tid];
    sbias[tid + 64] = b1[tid];

    float4 acc[4];
    #pragma unroll
    for (int u = 0; u < 4; u++) acc[u] = make_float4(0.f, 0.f, 0.f, 0.f);

    for (int c0 = 0; c0 < nnz; c0 += 64) {
        int n = min(64, nnz - c0);
        if (tid < n) se[tid] = g_edge[base + c0 + tid];
        __syncthreads();
        int e = w;
        for (; e + 6 < n; e += 8) {
            #pragma unroll
            for (int u = 0; u < 4; u++) {
                Edge ed = se[e + 2 * u];
                float4 p = AB4[(size_t)ed.c * 32 + l];
                acc[u].x += ed.v * p.x; acc[u].y += ed.v * p.y;
                acc[u].z += ed.v * p.z; acc[u].w += ed.v * p.w;
            }
        }
        for (; e < n; e += 2) {
            Edge ed = se[e];
            float4 p = AB4[(size_t)ed.c * 32 + l];
            acc[0].x += ed.v * p.x; acc[0].y += ed.v * p.y;
            acc[0].z += ed.v * p.z; acc[0].w += ed.v * p.w;
        }
        __syncthreads();
    }
    float4 sum;
    sum.x = acc[0].x + acc[1].x + acc[2].x + acc[3].x;
    sum.y = acc[0].y + acc[1].y + acc[2].y + acc[3].y;
    sum.z = acc[0].z + acc[1].z + acc[2].z + acc[3].z;
    sum.w = acc[0].w + acc[1].w + acc[2].w + acc[3].w;

    if (w == 1) red[l] = sum;
    __syncthreads();
    if (w == 0) {
        float4 o = red[l];
        float4 bv = *(const float4*)&sbias[l * 4];
        sum.x = fmaxf(sum.x + o.x + bv.x, 0.f);
        sum.y = fmaxf(sum.y + o.y + bv.y, 0.f);
        sum.z = fmaxf(sum.z + o.z + bv.z, 0.f);
        sum.w = fmaxf(sum.w + o.w + bv.w, 0.f);
        ((float4*)g_CD)[(size_t)row * 32 + l] = sum;
        if (layer2) *(float4*)&srep[l * 4] = sum;
    }

    if (layer2) {
        __syncthreads();
        float rs = srep[tid] * a[tid]       + srep[64 + tid] * a[64 + tid];
        float rd = srep[tid] * a[128 + tid] + srep[64 + tid] * a[192 + tid];
        #pragma unroll
        for (int o = 16; o; o >>= 1) {
            rs += __shfl_xor_sync(0xffffffffu, rs, o);
            rd += __shfl_xor_sync(0xffffffffu, rd, o);
        }
        if (l == 0) { xr[w] = rs; xd[w] = rd; }
        __syncthreads();
        if (tid == 0) { g_ssrc[row] = xr[0] + xr[1]; g_sdst[row] = xd[0] + xd[1]; }
    }
}

// ---------------- column sum of rep_t: one kernel, last-block combines ----------------
__global__ void k_colsum() {
    int b = blockIdx.x;   // 250 blocks x 40 rows
    int h = threadIdx.x;  // 64
    int r0 = b * 40;
    float acc = 0.f;
    #pragma unroll 4
    for (int r = r0; r < r0 + 40; r++) acc += g_CD[(size_t)r * 128 + 64 + h];
    g_part[b * 64 + h] = acc;
    __threadfence();
    __syncthreads();
    __shared__ int last;
    if (h == 0) last = atomicAdd(&g_ccnt, 1);
    __syncthreads();
    if (last == 249) {
        __threadfence();
        float s = 0.f;
        for (int i = 0; i < 250; i++) s += g_part[i * 64 + h];   // fixed order: deterministic
        g_Sall[h] = s;
        if (h == 0) g_ccnt = 0;   // re-arm for next replay
    }
}

// ---------------- attention: half-warp float4 gather (R10) ----------------
__global__ void k_att(float* __restrict__ dout) {
    int row = blockIdx.x * 2 + threadIdx.y;
    int l = threadIdx.x;
    int half = l >> 4, q = l & 15;
    int base = g_rowbase[row], nnz = g_rownnz[row];
    float si = g_ssrc[row];

    float lm = -1e30f;
    for (int e = l; e < nnz; e += 32)
        lm = fmaxf(lm, g_sdst[g_edge[base + e].c]);
    #pragma unroll
    for (int o = 16; o; o >>= 1)
        lm = fmaxf(lm, __shfl_xor_sync(0xffffffffu, lm, o));
    float mm = fmaxf(si + lm, 0.f);

    const float4* __restrict__ CD4 = (const float4*)g_CD;
    float4 aW0 = {0.f,0.f,0.f,0.f}, aW1 = aW0, aR0 = aW0, aR1 = aW0;
    float sw = 0.f;
    int e = half;
    for (; e + 2 < nnz; e += 4) {
        int c0 = g_edge[base + e].c;
        int c1 = g_edge[base + e + 2].c;
        float w0 = __expf(si + g_sdst[c0] - mm);
        float w1 = __expf(si + g_sdst[c1] - mm);
        float4 p0 = CD4[(size_t)c0 * 32 + 16 + q];
        float4 p1 = CD4[(size_t)c1 * 32 + 16 + q];
        aW0.x += w0 * p0.x; aW0.y += w0 * p0.y; aW0.z += w0 * p0.z; aW0.w += w0 * p0.w;
        aW1.x += w1 * p1.x; aW1.y += w1 * p1.y; aW1.z += w1 * p1.z; aW1.w += w1 * p1.w;
        aR0.x += p0.x; aR0.y += p0.y; aR0.z += p0.z; aR0.w += p0.w;
        aR1.x += p1.x; aR1.y += p1.y; aR1.z += p1.z; aR1.w += p1.w;
        sw += w0 + w1;
    }
    for (; e < nnz; e += 2) {
        int cc = g_edge[base + e].c;
        float wt = __expf(si + g_sdst[cc] - mm);
        float4 p = CD4[(size_t)cc * 32 + 16 + q];
        aW0.x += wt * p.x; aW0.y += wt * p.y; aW0.z += wt * p.z; aW0.w += wt * p.w;
        aR0.x += p.x; aR0.y += p.y; aR0.z += p.z; aR0.w += p.w;
        sw += wt;
    }
    float4 aW, aR;
    aW.x = aW0.x + aW1.x; aW.y = aW0.y + aW1.y; aW.z = aW0.z + aW1.z; aW.w = aW0.w + aW1.w;
    aR.x = aR0.x + aR1.x; aR.y = aR0.y + aR1.y; aR.z = aR0.z + aR1.z; aR.w = aR0.w + aR1.w;

    sw   += __shfl_xor_sync(0xffffffffu, sw, 16);
    aW.x += __shfl_xor_sync(0xffffffffu, aW.x, 16);
    aW.y += __shfl_xor_sync(0xffffffffu, aW.y, 16);
    aW.z += __shfl_xor_sync(0xffffffffu, aW.z, 16);
    aW.w += __shfl_xor_sync(0xffffffffu, aW.w, 16);
    aR.x += __shfl_xor_sync(0xffffffffu, aR.x, 16);
    aR.y += __shfl_xor_sync(0xffffffffu, aR.y, 16);
    aR.z += __shfl_xor_sync(0xffffffffu, aR.z, 16);
    aR.w += __shfl_xor_sync(0xffffffffu, aR.w, 16);

    float em = __expf(-mm);
    float denom = (float)(NN - nnz) * em + sw;
    if (half == 0) {
        float4 S = ((const float4*)g_Sall)[q];
        float4 C = CD4[(size_t)row * 32 + q];
        float4 v;
        v.x = (em * (S.x - aR.x) + aW.x) / denom + C.x;
        v.y = (em * (S.y - aR.y) + aW.y) / denom + C.y;
        v.z = (em * (S.z - aR.z) + aW.z) / denom + C.z;
        v.w = (em * (S.w - aR.w) + aW.w) / denom + C.w;
        ((float4*)(dout + 10000))[(size_t)row * 16 + q] = v;
        ((float4*)g_R)[(size_t)row * 16 + q] = v;
    }
}

// ---------------- heads: 3-way block split (path0 / path1 / treatment) ----------------
__global__ void __launch_bounds__(256) k_heads(
        const int* __restrict__ t,
        const float* __restrict__ W000, const float* __restrict__ b000,
        const float* __restrict__ W001, const float* __restrict__ b001,
        const float* __restrict__ W100, const float* __restrict__ b100,
        const float* __restrict__ W101, const float* __restrict__ b101,
        const float* __restrict__ Wo0,  const float* __restrict__ bo0,
        const float* __restrict__ Wo1,  const float* __restrict__ bo1,
        const float* __restrict__ Wpp,  const float* __restrict__ bpp,
        const float* __restrict__ Wpp2, const float* __restrict__ bpp2,
        float* __restrict__ dout) {
    __shared__ float U[64 * 65];
    __shared__ float V[64 * 65];
    __shared__ float Ws[64 * 64];
    __shared__ float sWv[64];

    int tid = threadIdx.x;
    int tx = tid & 15, ty = tid >> 4;
    int r0 = blockIdx.x * 64;
    int p = blockIdx.y;

    auto loadW = [&](const float* W) {
        const float4* s = (const float4*)W;
        float4* d = (float4*)Ws;
        #pragma unroll
        for (int i = 0; i < 4; i++) d[tid + 256 * i] = s[tid + 256 * i];
    };
    auto loadX = [&](const float* X, int stride) {
        #pragma unroll
        for (int i = 0; i < 4; i++) {
            int e = tid + 256 * i;
            int row = e >> 4, c4 = e & 15;
            float4 v = ((const float4*)(X + (size_t)(r0 + row) * stride))[c4];
            U[row * 65 + c4 * 4 + 0] = v.x;
            U[row * 65 + c4 * 4 + 1] = v.y;
            U[row * 65 + c4 * 4 + 2] = v.z;
            U[row * 65 + c4 * 4 + 3] = v.w;
        }
    };
    auto stage = [&](const float* in, float* outp, const float* b, bool relu) {
        float acc[4][4] = {};
        #pragma unroll 4
        for (int k = 0; k < 64; k++) {
            float4 wv = *(const float4*)&Ws[k * 64 + tx * 4];
            float xv[4];
            #pragma unroll
            for (int i = 0; i < 4; i++) xv[i] = in[(ty * 4 + i) * 65 + k];
            #pragma unroll
            for (int i = 0; i < 4; i++) {
                acc[i][0] += xv[i] * wv.x; acc[i][1] += xv[i] * wv.y;
                acc[i][2] += xv[i] * wv.z; acc[i][3] += xv[i] * wv.w;
            }
        }
        #pragma unroll
        for (int i = 0; i < 4; i++)
            #pragma unroll
            for (int j = 0; j < 4; j++) {
                float vv = acc[i][j] + b[tx * 4 + j];
                if (relu) vv = fmaxf(vv, 0.f);
                outp[(ty * 4 + i) * 65 + tx * 4 + j] = vv;
            }
    };

    if (p == 2) {
        // ===== treatment head: rep_t @ Wpp + bpp (no relu), @ Wpp2, sigmoid =====
        loadX((const float*)g_CD + 64, 128);
        loadW(Wpp);
        __syncthreads();
        stage(U, V, bpp, false);
        __syncthreads();
        if (tid < 64) {
            int row = r0 + tid;
            if (row < NN) {
                float z0 = 0.f, z1 = 0.f;
                #pragma unroll 4
                for (int k = 0; k < 64; k++) {
                    float e = V[tid * 65 + k];
                    z0 += e * Wpp2[k * 2];
                    z1 += e * Wpp2[k * 2 + 1];
                }
                dout[650000 + (size_t)row * 2 + 0] = 1.f / (1.f + __expf(-(z0 + bpp2[0])));
                dout[650000 + (size_t)row * 2 + 1] = 1.f / (1.f + __expf(-(z1 + bpp2[1])));
            }
        }
        // re-arm edge pool for next graph replay (runs exactly once: block x==0 of role 2)
        if (blockIdx.x == 0 && tid == 0) g_top = 0;
        return;
    }

    // ===== outcome path p: rep_out @ Wp00 -> relu -> @Wp01 -> relu -> .Wop =====
    const float* Wa = p ? W100 : W000;
    const float* ba = p ? b100 : b000;
    const float* Wb = p ? W101 : W001;
    const float* bb = p ? b101 : b001;
    const float* Wo = p ? Wo1  : Wo0;
    float bo = p ? bo1[0] : bo0[0];

    loadX((const float*)g_R, 64);
    loadW(Wa);
    if (tid < 64) sWv[tid] = Wo[tid];
    __syncthreads();
    stage(U, V, ba, true);
    __syncthreads();
    loadW(Wb);
    __syncthreads();
    stage(V, U, bb, true);
    __syncthreads();

    if (tid < 64) {
        int row = r0 + tid;
        if (row < NN && (t[row] > 0) == (p == 1)) {
            float acc = 0.f;
            #pragma unroll 4
            for (int k = 0; k < 64; k++) acc += U[tid * 65 + k] * sWv[k];
            dout[row] = acc + bo;
        }
    }
}

// ---------------- launch ----------------
extern "C" void kernel_launch(void* const* d_in, const int* in_sizes, int n_in,
                              void* d_out, int out_size) {
    const float* x    = (const float*)d_in[0];
    const float* adj  = (const float*)d_in[1];
    const int*   t    = (const int*)d_in[2];
    const float* Wg0  = (const float*)d_in[3];
    const float* bg0  = (const float*)d_in[4];
    const float* Wg1  = (const float*)d_in[5];
    const float* bg1  = (const float*)d_in[6];
    const float* Wt0  = (const float*)d_in[7];
    const float* bt0  = (const float*)d_in[8];
    const float* Wt1  = (const float*)d_in[9];
    const float* bt1  = (const float*)d_in[10];
    const float* W000 = (const float*)d_in[11];
    const float* b000 = (const float*)d_in[12];
    const float* W001 = (const float*)d_in[13];
    const float* b001 = (const float*)d_in[14];
    const float* W100 = (const float*)d_in[15];
    const float* b100 = (const float*)d_in[16];
    const float* W101 = (const float*)d_in[17];
    const float* b101 = (const float*)d_in[18];
    const float* Wo0  = (const float*)d_in[19];
    const float* bo0  = (const float*)d_in[20];
    const float* Wo1  = (const float*)d_in[21];
    const float* bo1  = (const float*)d_in[22];
    const float* Wpp  = (const float*)d_in[23];
    const float* bpp  = (const float*)d_in[24];
    const float* Wpp2 = (const float*)d_in[25];
    const float* bpp2 = (const float*)d_in[26];
    const float* a    = (const float*)d_in[27];
    float* out = (float*)d_out;

    float* pAB; cudaGetSymbolAddress((void**)&pAB, g_AB);
    float* pCD; cudaGetSymbolAddress((void**)&pCD, g_CD);

    // merged sparsify + layer-1 GEMM
    {
        GemmArgs ga = {};
        ga.X[0] = x;   ga.X[1] = x;
        ga.W[0] = Wg0; ga.W[1] = Wt0;
        ga.out[0] = pAB; ga.out[1] = pAB + 64;
        ga.xs = 128;
        k_spg<<<NN + 626, 256>>>(adj, ga);
    }
    k_spmm<<<NN, 64>>>(bg0, bt0, 0, nullptr);

    // layer 2
    {
        GemmArgs ga = {};
        ga.X[0] = pCD;  ga.X[1] = pCD + 64;
        ga.W[0] = Wg1; ga.W[1] = Wt1;
        ga.out[0] = pAB; ga.out[1] = pAB + 64;
        ga.xs = 128;
        k_gemm<64><<<dim3(313, 2), 256>>>(ga);
    }
    k_spmm<<<NN, 64>>>(bg1, bt1, 1, a);   // + fused scores

    k_colsum<<<250, 64>>>();
    k_att<<<5000, dim3(32, 2)>>>(out);

    k_heads<<<dim3(157, 3), 256>>>(t, W000, b000, W001, b001, W100, b100, W101, b101,
                                   Wo0, bo0, Wo1, bo1, Wpp, bpp, Wpp2, bpp2, out);
}